// round 7
// baseline (speedup 1.0000x reference)
#include <cuda_runtime.h>
#include <cuda_bf16.h>
#include <math.h>
#include <stdint.h>

#define B_ 1024
#define D_ 1024
#define H_ 4096
#define C_ 5120
#define LN_EPS 1e-3f
#define KSLICE_D 4

// ---------------- scratch (device globals: allocation-free) ----------------
__device__ __align__(1024) __nv_bfloat16 g_a1h[B_ * C_], g_a1l[B_ * C_];
__device__ __align__(1024) __nv_bfloat16 g_a2h[B_ * C_], g_a2l[B_ * C_];
__device__ __align__(1024) __nv_bfloat16 g_a3h[B_ * H_], g_a3l[B_ * H_];
__device__ __align__(1024) __nv_bfloat16 g_wuh[(long)H_ * C_],  g_wul[(long)H_ * C_];
__device__ __align__(1024) __nv_bfloat16 g_wrh[(long)H_ * C_],  g_wrl[(long)H_ * C_];
__device__ __align__(1024) __nv_bfloat16 g_wgh[(long)H_ * C_],  g_wgl[(long)H_ * C_];
__device__ __align__(1024) __nv_bfloat16 g_wph[(long)H_ * C_],  g_wpl[(long)H_ * C_];
__device__ __align__(1024) __nv_bfloat16 g_wdh[(long)D_ * H_],  g_wdl[(long)D_ * H_];
__device__ float g_u [B_ * H_];
__device__ float g_g [B_ * H_];
__device__ float g_up[B_ * H_];
__device__ float g_nh[B_ * H_];
__device__ float g_do[KSLICE_D * B_ * D_];

// ---------------- helpers ----------------
__device__ __forceinline__ uint32_t smem_u32(const void* p) {
    uint32_t a;
    asm("{ .reg .u64 t; cvta.to.shared.u64 t, %1; cvt.u32.u64 %0, t; }" : "=r"(a) : "l"(p));
    return a;
}
__device__ __forceinline__ void cp16(uint32_t dst, const void* src) {
    asm volatile("cp.async.cg.shared.global [%0], [%1], 16;" :: "r"(dst), "l"(src) : "memory");
}
__device__ __forceinline__ void ldsm_x4(uint32_t* r, uint32_t addr) {
    asm volatile("ldmatrix.sync.aligned.m8n8.x4.shared.b16 {%0,%1,%2,%3}, [%4];"
                 : "=r"(r[0]), "=r"(r[1]), "=r"(r[2]), "=r"(r[3]) : "r"(addr));
}
__device__ __forceinline__ void mma16816(float* c, const uint32_t* a, uint32_t b0, uint32_t b1) {
    asm volatile(
        "mma.sync.aligned.m16n8k16.row.col.f32.bf16.bf16.f32 "
        "{%0,%1,%2,%3}, {%4,%5,%6,%7}, {%8,%9}, {%0,%1,%2,%3};"
        : "+f"(c[0]), "+f"(c[1]), "+f"(c[2]), "+f"(c[3])
        : "r"(a[0]), "r"(a[1]), "r"(a[2]), "r"(a[3]), "r"(b0), "r"(b1));
}
__device__ __forceinline__ void split_bf(float f, __nv_bfloat16& hi, __nv_bfloat16& lo) {
    hi = __float2bfloat16(f);
    lo = __float2bfloat16(f - __bfloat162float(hi));
}
__device__ __forceinline__ float sigm(float x) { return 1.0f / (1.0f + expf(-x)); }

// swizzled offset inside a [128 rows][32 bf16] tile (64B rows, 16B chunks)
__device__ __forceinline__ uint32_t sw_off(int row, int cb) {
    return (uint32_t)row * 64u + (uint32_t)((cb ^ ((row >> 1) & 3)) << 4);
}

// ---------------- split-bf16 HMMA GEMM (2 CTAs/SM, 1 barrier/stage) ----------------
#define KT 32
#define STG 3
#define STAGE_BYTES 32768u   // 4 tiles of 128x32 bf16 (8KB each)
// tile offsets within a stage: Ah 0, Al 8192, Bh 16384, Bl 24576

template<int MODE>
__global__ void __launch_bounds__(256, 2) gemm_hmma(
    const __nv_bfloat16* __restrict__ Ah, const __nv_bfloat16* __restrict__ Al, int ldA,
    const __nv_bfloat16* __restrict__ B0h, const __nv_bfloat16* __restrict__ B0l,
    const __nv_bfloat16* __restrict__ B1h, const __nv_bfloat16* __restrict__ B1l, int ldB,
    const float* __restrict__ bias0, const float* __restrict__ bias1,
    const float* __restrict__ hmul,
    float* __restrict__ fout0, float* __restrict__ fout1,
    __nv_bfloat16* __restrict__ obh, __nv_bfloat16* __restrict__ obl,
    int K, int nhalf, int kslices)
{
    extern __shared__ __align__(1024) char smraw[];
    const uint32_t sb = smem_u32(smraw);

    const int tid = threadIdx.x, lane = tid & 31, wid = tid >> 5;
    const int wm = (wid >> 2) * 64;   // warp M offset (0 / 64)
    const int wn = (wid & 3) * 32;    // warp N offset (0/32/64/96)
    const int nt = blockIdx.x, mt = blockIdx.y;
    const bool second = nt >= nhalf;
    const int ntin = second ? nt - nhalf : nt;
    const __nv_bfloat16* Bhp = second ? B1h : B0h;
    const __nv_bfloat16* Blp = second ? B1l : B0l;
    const float* bias = second ? bias1 : bias0;

    const int m0 = mt * 128, n0 = ntin * 128;
    const int Ks = K / kslices;
    const int kbeg = blockIdx.z * Ks;
    const int S = Ks / KT;

    // ---- stage loader ----
    const int lr  = tid >> 1;            // row 0..127
    const int lcb = (tid & 1) * 2;       // chunk base 0 or 2
    auto load_stage = [&](int slot, int kk) {
        const uint32_t tb = sb + (uint32_t)slot * STAGE_BYTES;
        const size_t arow = (size_t)(m0 + lr) * ldA + kk;
        const size_t brow = (size_t)(n0 + lr) * ldB + kk;
#pragma unroll
        for (int c = 0; c < 2; c++) {
            const int cb = lcb + c;
            const uint32_t sw = tb + sw_off(lr, cb);
            cp16(sw,          Ah  + arow + cb * 8);
            cp16(sw + 8192,   Al  + arow + cb * 8);
            cp16(sw + 16384,  Bhp + brow + cb * 8);
            cp16(sw + 24576,  Blp + brow + cb * 8);
        }
    };

    // ---- precomputed ldsm offsets (s=0 chunk; s=1 is off ^ 32) ----
    const int lb = (lane >> 4) & 1;
    uint32_t offA[4], offB[2];
#pragma unroll
    for (int i = 0; i < 4; i++) offA[i] = sw_off(wm + i * 16 + (lane & 15), lb);
#pragma unroll
    for (int jp = 0; jp < 2; jp++) offB[jp] = sw_off(wn + jp * 16 + (lane & 15), lb);

    // prologue: stages 0..STG-2
#pragma unroll
    for (int s = 0; s < STG - 1; s++) {
        if (s < S) load_stage(s, kbeg + s * KT);
        asm volatile("cp.async.commit_group;" ::: "memory");
    }

    float acc[4][4][4];
#pragma unroll
    for (int i = 0; i < 4; i++)
#pragma unroll
        for (int j = 0; j < 4; j++)
#pragma unroll
            for (int e = 0; e < 4; e++) acc[i][j][e] = 0.f;

    for (int ks = 0; ks < S; ks++) {
        asm volatile("cp.async.wait_group 1;" ::: "memory");
        __syncthreads();
        // fill the slot freed by the barrier above (stage ks-1's slot)
        if (ks + STG - 1 < S) load_stage((ks + STG - 1) % STG, kbeg + (ks + STG - 1) * KT);
        asm volatile("cp.async.commit_group;" ::: "memory");

        const uint32_t base = sb + (uint32_t)(ks % STG) * STAGE_BYTES;
#pragma unroll
        for (int s = 0; s < 2; s++) {
            const uint32_t sx = (uint32_t)(s << 5);
            uint32_t ah[4][4], bh[2][4], bl[2][4];
#pragma unroll
            for (int i = 0; i < 4; i++)  ldsm_x4(ah[i], base + (offA[i] ^ sx));
#pragma unroll
            for (int jp = 0; jp < 2; jp++) ldsm_x4(bh[jp], base + 16384 + (offB[jp] ^ sx));
#pragma unroll
            for (int jp = 0; jp < 2; jp++) ldsm_x4(bl[jp], base + 24576 + (offB[jp] ^ sx));
            // term hh
#pragma unroll
            for (int i = 0; i < 4; i++)
#pragma unroll
                for (int j = 0; j < 4; j++)
                    mma16816(acc[i][j], ah[i], bh[j >> 1][j & 1], bh[j >> 1][2 | (j & 1)]);
            // prefetch al under the hh MMAs
            uint32_t al[4][4];
#pragma unroll
            for (int i = 0; i < 4; i++)  ldsm_x4(al[i], base + 8192 + (offA[i] ^ sx));
            // term h*l
#pragma unroll
            for (int i = 0; i < 4; i++)
#pragma unroll
                for (int j = 0; j < 4; j++)
                    mma16816(acc[i][j], ah[i], bl[j >> 1][j & 1], bl[j >> 1][2 | (j & 1)]);
            // term l*h
#pragma unroll
            for (int i = 0; i < 4; i++)
#pragma unroll
                for (int j = 0; j < 4; j++)
                    mma16816(acc[i][j], al[i], bh[j >> 1][j & 1], bh[j >> 1][2 | (j & 1)]);
        }
    }

    // ---- epilogue ----
#pragma unroll
    for (int i = 0; i < 4; i++) {
#pragma unroll
        for (int j = 0; j < 4; j++) {
            const int r0 = m0 + wm + i * 16 + (lane >> 2);
            const int gc = ntin * 128 + wn + j * 8 + 2 * (lane & 3);
#pragma unroll
            for (int half = 0; half < 2; half++) {
                const int row = r0 + half * 8;
                const float v0r = acc[i][j][half * 2];
                const float v1r = acc[i][j][half * 2 + 1];
                if (MODE == 0) {
                    const float v0 = v0r + bias[gc], v1 = v1r + bias[gc + 1];
                    if (!second) {
                        fout0[(long)row * H_ + gc]     = sigm(v0);
                        fout0[(long)row * H_ + gc + 1] = sigm(v1);
                    } else {
                        const float rh0 = sigm(v0) * hmul[(long)row * H_ + gc];
                        const float rh1 = sigm(v1) * hmul[(long)row * H_ + gc + 1];
                        __nv_bfloat16 h0, l0, h1, l1;
                        split_bf(rh0, h0, l0);
                        split_bf(rh1, h1, l1);
                        obh[(long)row * C_ + D_ + gc]     = h0;
                        obl[(long)row * C_ + D_ + gc]     = l0;
                        obh[(long)row * C_ + D_ + gc + 1] = h1;
                        obl[(long)row * C_ + D_ + gc + 1] = l1;
                    }
                } else if (MODE == 1) {
                    float* dst = second ? fout1 : fout0;
                    dst[(long)row * H_ + gc]     = v0r + bias[gc];
                    dst[(long)row * H_ + gc + 1] = v1r + bias[gc + 1];
                } else {
                    float* dst = fout0 + (size_t)blockIdx.z * B_ * D_;
                    dst[(long)row * D_ + gc]     = v0r;
                    dst[(long)row * D_ + gc + 1] = v1r;
                }
            }
        }
    }
}

// ---------------- conversion kernels ----------------
__global__ void conv_a1(const float* __restrict__ x, const float* __restrict__ h,
                        __nv_bfloat16* __restrict__ a1h, __nv_bfloat16* __restrict__ a1l,
                        __nv_bfloat16* __restrict__ a2h, __nv_bfloat16* __restrict__ a2l)
{
    const long i4 = (long)blockIdx.x * blockDim.x + threadIdx.x;
    if (i4 >= (long)B_ * C_ / 4) return;
    const int row = (int)(i4 / (C_ / 4));
    const int c = (int)(i4 % (C_ / 4)) * 4;
    float4 f;
    if (c < D_) f = *(const float4*)(x + (long)row * D_ + c);
    else        f = *(const float4*)(h + (long)row * H_ + (c - D_));
    __nv_bfloat16 h0, l0, h1, l1, h2, l2, h3, l3;
    split_bf(f.x, h0, l0); split_bf(f.y, h1, l1);
    split_bf(f.z, h2, l2); split_bf(f.w, h3, l3);
    __nv_bfloat162 hv0 = {h0, h1}, hv1 = {h2, h3};
    __nv_bfloat162 lv0 = {l0, l1}, lv1 = {l2, l3};
    const long o = (long)row * C_ + c;
    *(uint2*)(a1h + o) = make_uint2(*(uint32_t*)&hv0, *(uint32_t*)&hv1);
    *(uint2*)(a1l + o) = make_uint2(*(uint32_t*)&lv0, *(uint32_t*)&lv1);
    if (c < D_) {
        *(uint2*)(a2h + o) = make_uint2(*(uint32_t*)&hv0, *(uint32_t*)&hv1);
        *(uint2*)(a2l + o) = make_uint2(*(uint32_t*)&lv0, *(uint32_t*)&lv1);
    }
}

// batched transpose + split for the 4 big weights
__global__ void tconv4(const float* __restrict__ s0, const float* __restrict__ s1,
                       const float* __restrict__ s2, const float* __restrict__ s3,
                       __nv_bfloat16* __restrict__ d0h, __nv_bfloat16* __restrict__ d0l,
                       __nv_bfloat16* __restrict__ d1h, __nv_bfloat16* __restrict__ d1l,
                       __nv_bfloat16* __restrict__ d2h, __nv_bfloat16* __restrict__ d2l,
                       __nv_bfloat16* __restrict__ d3h, __nv_bfloat16* __restrict__ d3l)
{
    const int z = blockIdx.z;
    const float* src = z == 0 ? s0 : z == 1 ? s1 : z == 2 ? s2 : s3;
    __nv_bfloat16* dh = z == 0 ? d0h : z == 1 ? d1h : z == 2 ? d2h : d3h;
    __nv_bfloat16* dl = z == 0 ? d0l : z == 1 ? d1l : z == 2 ? d2l : d3l;
    const int K = C_, N = H_;

    __shared__ float t[64][33];
    const int kt = blockIdx.y * 64, nb = blockIdx.x * 32;
    const int tid = threadIdx.x;
    {
        const int c4 = (tid & 7) * 4, r0 = tid >> 3;
#pragma unroll
        for (int p = 0; p < 2; p++) {
            const int r = r0 + p * 32;
            const float4 f = *(const float4*)(src + (long)(kt + r) * N + nb + c4);
            t[r][c4] = f.x; t[r][c4 + 1] = f.y; t[r][c4 + 2] = f.z; t[r][c4 + 3] = f.w;
        }
    }
    __syncthreads();
    const int n  = tid >> 3;
    const int k8 = (tid & 7) * 8;
    __nv_bfloat162 hv[4], lv[4];
#pragma unroll
    for (int i = 0; i < 4; i++) {
        const float f0 = t[k8 + 2 * i][n], f1 = t[k8 + 2 * i + 1][n];
        __nv_bfloat16 h0, l0, h1, l1;
        split_bf(f0, h0, l0);
        split_bf(f1, h1, l1);
        hv[i] = {h0, h1};
        lv[i] = {l0, l1};
    }
    const long o = (long)(nb + n) * K + kt + k8;
    *(uint4*)(dh + o) = make_uint4(*(uint32_t*)&hv[0], *(uint32_t*)&hv[1],
                                   *(uint32_t*)&hv[2], *(uint32_t*)&hv[3]);
    *(uint4*)(dl + o) = make_uint4(*(uint32_t*)&lv[0], *(uint32_t*)&lv[1],
                                   *(uint32_t*)&lv[2], *(uint32_t*)&lv[3]);
}

__global__ void tconv(const float* __restrict__ src,
                      __nv_bfloat16* __restrict__ dh, __nv_bfloat16* __restrict__ dl,
                      int K, int N)
{
    __shared__ float t[64][33];
    const int kt = blockIdx.y * 64, nb = blockIdx.x * 32;
    const int tid = threadIdx.x;
    {
        const int c4 = (tid & 7) * 4, r0 = tid >> 3;
#pragma unroll
        for (int p = 0; p < 2; p++) {
            const int r = r0 + p * 32;
            const float4 f = *(const float4*)(src + (long)(kt + r) * N + nb + c4);
            t[r][c4] = f.x; t[r][c4 + 1] = f.y; t[r][c4 + 2] = f.z; t[r][c4 + 3] = f.w;
        }
    }
    __syncthreads();
    const int n  = tid >> 3;
    const int k8 = (tid & 7) * 8;
    __nv_bfloat162 hv[4], lv[4];
#pragma unroll
    for (int i = 0; i < 4; i++) {
        const float f0 = t[k8 + 2 * i][n], f1 = t[k8 + 2 * i + 1][n];
        __nv_bfloat16 h0, l0, h1, l1;
        split_bf(f0, h0, l0);
        split_bf(f1, h1, l1);
        hv[i] = {h0, h1};
        lv[i] = {l0, l1};
    }
    const long o = (long)(nb + n) * K + kt + k8;
    *(uint4*)(dh + o) = make_uint4(*(uint32_t*)&hv[0], *(uint32_t*)&hv[1],
                                   *(uint32_t*)&hv[2], *(uint32_t*)&hv[3]);
    *(uint4*)(dl + o) = make_uint4(*(uint32_t*)&lv[0], *(uint32_t*)&lv[1],
                                   *(uint32_t*)&lv[2], *(uint32_t*)&lv[3]);
}

// ---------------- LayerNorm kernels ----------------
__global__ void ln_newh(const float* __restrict__ u, const float* __restrict__ h,
                        const float* __restrict__ g, const float* __restrict__ up,
                        const float* __restrict__ gamma, const float* __restrict__ beta,
                        float* __restrict__ out,
                        __nv_bfloat16* __restrict__ a3h, __nv_bfloat16* __restrict__ a3l)
{
    const int row = blockIdx.x, tid = threadIdx.x;
    const int PER = H_ / 256;
    const long base = (long)row * H_;
    float v[PER];
    float s = 0.f, ss = 0.f;
#pragma unroll
    for (int i = 0; i < PER; i++) {
        const int j = i * 256 + tid;
        const float uu = u[base + j];
        const float gg = g[base + j];
        const float val = h[base + j] * (2.f - uu) + uu * (gg * sigm(gg)) * up[base + j];
        v[i] = val; s += val; ss += val * val;
    }
    __shared__ float sm[2][8];
#pragma unroll
    for (int o = 16; o > 0; o >>= 1) {
        s  += __shfl_xor_sync(0xffffffffu, s, o);
        ss += __shfl_xor_sync(0xffffffffu, ss, o);
    }
    const int warp = tid >> 5, lane = tid & 31;
    if (lane == 0) { sm[0][warp] = s; sm[1][warp] = ss; }
    __syncthreads();
    float ts = 0.f, tss = 0.f;
#pragma unroll
    for (int w = 0; w < 8; w++) { ts += sm[0][w]; tss += sm[1][w]; }
    const float mean = ts / (float)H_;
    const float var  = tss / (float)H_ - mean * mean;
    const float rstd = rsqrtf(var + LN_EPS);
#pragma unroll
    for (int i = 0; i < PER; i++) {
        const int j = i * 256 + tid;
        const float r = (v[i] - mean) * rstd * gamma[j] + beta[j];
        out[base + j] = r;
        __nv_bfloat16 hi, lo;
        split_bf(r, hi, lo);
        a3h[base + j] = hi; a3l[base + j] = lo;
    }
}

__global__ void ln_out(const float* __restrict__ in,
                       const float* __restrict__ bd,
                       const float* __restrict__ gamma, const float* __restrict__ beta,
                       float* __restrict__ out)
{
    const int row = blockIdx.x, tid = threadIdx.x;
    const int PER = D_ / 256;
    const long base = (long)row * D_;
    const long zoff = (long)B_ * D_;
    float v[PER];
    float s = 0.f, ss = 0.f;
#pragma unroll
    for (int i = 0; i < PER; i++) {
        const int j = i * 256 + tid;
        float val = bd[j];
#pragma unroll
        for (int z = 0; z < KSLICE_D; z++) val += in[z * zoff + base + j];
        v[i] = val; s += val; ss += val * val;
    }
    __shared__ float sm[2][8];
#pragma unroll
    for (int o = 16; o > 0; o >>= 1) {
        s  += __shfl_xor_sync(0xffffffffu, s, o);
        ss += __shfl_xor_sync(0xffffffffu, ss, o);
    }
    const int warp = tid >> 5, lane = tid & 31;
    if (lane == 0) { sm[0][warp] = s; sm[1][warp] = ss; }
    __syncthreads();
    float ts = 0.f, tss = 0.f;
#pragma unroll
    for (int w = 0; w < 8; w++) { ts += sm[0][w]; tss += sm[1][w]; }
    const float mean = ts / (float)D_;
    const float var  = tss / (float)D_ - mean * mean;
    const float rstd = rsqrtf(var + LN_EPS);
#pragma unroll
    for (int i = 0; i < PER; i++) {
        const int j = i * 256 + tid;
        out[base + j] = (v[i] - mean) * rstd * gamma[j] + beta[j];
    }
}

// ---------------- host ----------------
extern "C" void kernel_launch(void* const* d_in, const int* in_sizes, int n_in,
                              void* d_out, int out_size)
{
    const float* x    = (const float*)d_in[0];
    const float* h    = (const float*)d_in[1];
    const float* W_u  = (const float*)d_in[2];
    const float* b_u  = (const float*)d_in[3];
    const float* W_r  = (const float*)d_in[4];
    const float* b_r  = (const float*)d_in[5];
    const float* W_g  = (const float*)d_in[6];
    const float* b_g  = (const float*)d_in[7];
    const float* W_up = (const float*)d_in[8];
    const float* b_up = (const float*)d_in[9];
    const float* W_d  = (const float*)d_in[10];
    const float* b_d  = (const float*)d_in[11];
    const float* g_h  = (const float*)d_in[12];
    const float* be_h = (const float*)d_in[13];
    const float* g_o  = (const float*)d_in[14];
    const float* be_o = (const float*)d_in[15];
    float* out = (float*)d_out;

    void *pa1h, *pa1l, *pa2h, *pa2l, *pa3h, *pa3l;
    void *pwuh, *pwul, *pwrh, *pwrl, *pwgh, *pwgl, *pwph, *pwpl, *pwdh, *pwdl;
    float *pu, *pg, *pup, *pnh, *pdo;
    cudaGetSymbolAddress(&pa1h, g_a1h); cudaGetSymbolAddress(&pa1l, g_a1l);
    cudaGetSymbolAddress(&pa2h, g_a2h); cudaGetSymbolAddress(&pa2l, g_a2l);
    cudaGetSymbolAddress(&pa3h, g_a3h); cudaGetSymbolAddress(&pa3l, g_a3l);
    cudaGetSymbolAddress(&pwuh, g_wuh); cudaGetSymbolAddress(&pwul, g_wul);
    cudaGetSymbolAddress(&pwrh, g_wrh); cudaGetSymbolAddress(&pwrl, g_wrl);
    cudaGetSymbolAddress(&pwgh, g_wgh); cudaGetSymbolAddress(&pwgl, g_wgl);
    cudaGetSymbolAddress(&pwph, g_wph); cudaGetSymbolAddress(&pwpl, g_wpl);
    cudaGetSymbolAddress(&pwdh, g_wdh); cudaGetSymbolAddress(&pwdl, g_wdl);
    cudaGetSymbolAddress((void**)&pu,  g_u);
    cudaGetSymbolAddress((void**)&pg,  g_g);
    cudaGetSymbolAddress((void**)&pup, g_up);
    cudaGetSymbolAddress((void**)&pnh, g_nh);
    cudaGetSymbolAddress((void**)&pdo, g_do);

    constexpr int SMEM = STG * (int)STAGE_BYTES;  // 98304 -> 2 CTAs/SM
    cudaFuncSetAttribute((const void*)gemm_hmma<0>, cudaFuncAttributeMaxDynamicSharedMemorySize, SMEM);
    cudaFuncSetAttribute((const void*)gemm_hmma<1>, cudaFuncAttributeMaxDynamicSharedMemorySize, SMEM);
    cudaFuncSetAttribute((const void*)gemm_hmma<2>, cudaFuncAttributeMaxDynamicSharedMemorySize, SMEM);

    float* newh = (out_size >= B_ * (D_ + H_)) ? (out + (long)B_ * D_) : pnh;

    conv_a1<<<(unsigned)(((long)B_ * C_ / 4 + 255) / 256), 256>>>(
        x, h, (__nv_bfloat16*)pa1h, (__nv_bfloat16*)pa1l,
        (__nv_bfloat16*)pa2h, (__nv_bfloat16*)pa2l);

    tconv4<<<dim3(H_ / 32, C_ / 64, 4), 256>>>(
        W_u, W_r, W_g, W_up,
        (__nv_bfloat16*)pwuh, (__nv_bfloat16*)pwul,
        (__nv_bfloat16*)pwrh, (__nv_bfloat16*)pwrl,
        (__nv_bfloat16*)pwgh, (__nv_bfloat16*)pwgl,
        (__nv_bfloat16*)pwph, (__nv_bfloat16*)pwpl);
    tconv<<<dim3(D_ / 32, H_ / 64), 256>>>(W_d, (__nv_bfloat16*)pwdh, (__nv_bfloat16*)pwdl, H_, D_);

    gemm_hmma<0><<<dim3(64, 8, 1), 256, SMEM>>>(
        (const __nv_bfloat16*)pa1h, (const __nv_bfloat16*)pa1l, C_,
        (const __nv_bfloat16*)pwuh, (const __nv_bfloat16*)pwul,
        (const __nv_bfloat16*)pwrh, (const __nv_bfloat16*)pwrl, C_,
        b_u, b_r, h, pu, nullptr,
        (__nv_bfloat16*)pa2h, (__nv_bfloat16*)pa2l, C_, 32, 1);

    gemm_hmma<1><<<dim3(64, 8, 1), 256, SMEM>>>(
        (const __nv_bfloat16*)pa2h, (const __nv_bfloat16*)pa2l, C_,
        (const __nv_bfloat16*)pwgh, (const __nv_bfloat16*)pwgl,
        (const __nv_bfloat16*)pwph, (const __nv_bfloat16*)pwpl, C_,
        b_g, b_up, nullptr, pg, pup, nullptr, nullptr, C_, 32, 1);

    ln_newh<<<B_, 256>>>(pu, h, pg, pup, g_h, be_h, newh,
                         (__nv_bfloat16*)pa3h, (__nv_bfloat16*)pa3l);

    gemm_hmma<2><<<dim3(8, 8, KSLICE_D), 256, SMEM>>>(
        (const __nv_bfloat16*)pa3h, (const __nv_bfloat16*)pa3l, H_,
        (const __nv_bfloat16*)pwdh, (const __nv_bfloat16*)pwdl,
        (const __nv_bfloat16*)pwdh, (const __nv_bfloat16*)pwdl, H_,
        b_d, b_d, nullptr, pdo, nullptr, nullptr, nullptr, H_, 1000, KSLICE_D);

    ln_out<<<B_, 256>>>(pdo, b_d, g_o, be_o, out);
}